// round 2
// baseline (speedup 1.0000x reference)
#include <cuda_runtime.h>
#include <cuda_bf16.h>
#include <cstdint>
#include <cstddef>

// Problem constants
#define BB 8
#define CH 128
#define HH 160
#define WW 288
#define SR 4          // search range
#define ND 81         // (2*SR+1)^2

// Tiling
#define TX 32         // tile width (pixels)
#define TY 8          // tile height (pixels)
#define PPT 8         // pixels per thread along x
#define XG (TX / PPT) // 4 x-groups
#define NDY 9         // dy values, one per warp
#define NTHREADS (32 * NDY)   // 288
#define CCHUNK 4      // channels per smem chunk
#define NCHUNK (CH / CCHUNK)  // 32

#define SSTRIDE 36            // src smem row stride (floats), conflict-free, 16B-mult
#define TSTRIDE 52            // tgt smem row stride (floats), conflict-free, 16B-mult
#define TROWS (TY + 2 * SR)   // 16
#define TCOLS (TX + 2 * SR)   // 40

#define NSRC4 (CCHUNK * TY * (TX / 4))       // 256 float4 per chunk
#define NTGT4 (CCHUNK * TROWS * (TCOLS / 4)) // 640 float4 per chunk

// Channel index for displacement (dy, dx) matching the torch module ordering.
__device__ __forceinline__ int chan_idx(int dy, int dx) {
    if (dy == 0 && dx == 0) return 0;
    if (dx == 0) { int i = dy < 0 ? -dy : dy; return 1 + (i - 1) * 20 + (dy < 0 ? 0 : 1); }
    if (dy == 0) { int i = dx < 0 ? -dx : dx; return 1 + (i - 1) * 20 + (dx < 0 ? 2 : 3); }
    int i = dy < 0 ? -dy : dy;
    int j = dx < 0 ? -dx : dx;
    int k = (dy < 0) ? (dx < 0 ? 0 : 2) : (dx > 0 ? 1 : 3);
    return 1 + (i - 1) * 20 + 4 + (j - 1) * 4 + k;
}

__device__ __forceinline__ void cp16(uint32_t saddr, const void* gsrc, int nbytes) {
    // 16B async copy; nbytes in {0,16}: 0 => pure zero-fill (zero-padding for free)
    asm volatile("cp.async.cg.shared.global [%0], [%1], 16, %2;\n"
                 :: "r"(saddr), "l"(gsrc), "r"(nbytes));
}
#define CP_COMMIT() asm volatile("cp.async.commit_group;\n" ::: "memory")
#define CP_WAIT1()  asm volatile("cp.async.wait_group 1;\n" ::: "memory")

__global__ void __launch_bounds__(NTHREADS, 1)
costvol_kernel(const float* __restrict__ src,
               const float* __restrict__ tgt,
               float* __restrict__ out)
{
    __shared__ float sSrc[2][CCHUNK][TY][SSTRIDE];
    __shared__ float sTgt[2][CCHUNK][TROWS][TSTRIDE];

    const int b   = blockIdx.z;
    const int ty0 = blockIdx.y * TY;
    const int tx0 = blockIdx.x * TX;

    const int tid  = threadIdx.x;
    const int warp = tid >> 5;        // 0..8 -> dy = warp - 4
    const int lane = tid & 31;
    const int xg   = lane & (XG - 1); // 0..3
    const int yy   = lane >> 2;       // 0..7
    const int dy   = warp - SR;

    const float* srcB = src + (size_t)b * CH * HH * WW;
    const float* tgtB = tgt + (size_t)b * CH * HH * WW;

    // Precompute per-thread load descriptors (chunk-invariant parts)
    // src: one float4 per thread for tid < 256
    const int sc  = tid >> 6;              // channel-in-chunk
    const int srr = (tid >> 3) & 7;        // row
    const int sx4 = tid & 7;               // float4 col
    const uint32_t srcSm0 = (uint32_t)__cvta_generic_to_shared(
        &sSrc[0][sc][srr][4 * sx4]);
    const float* srcG0 = srcB + (size_t)sc * (HH * WW) + (ty0 + srr) * WW + tx0 + 4 * sx4;

    // tgt: up to 3 float4s per thread (640 = 2*288 + 64)
    uint32_t tgtSm0[3];
    const float* tgtG0[3];
    int tgtOk[3];
    #pragma unroll
    for (int k = 0; k < 3; ++k) {
        int idx = tid + k * NTHREADS;
        tgtOk[k] = 0;
        tgtSm0[k] = 0;
        tgtG0[k] = tgtB;
        if (idx < NTGT4) {
            int c   = idx / (TROWS * (TCOLS / 4));   // /160
            int rem = idx - c * (TROWS * (TCOLS / 4));
            int r   = rem / (TCOLS / 4);             // /10
            int x4  = rem - r * (TCOLS / 4);
            int gy = ty0 + r - SR;
            int gx = tx0 + 4 * x4 - SR;
            bool inb = (gy >= 0) && (gy < HH) && (gx >= 0) && (gx <= WW - 4);
            tgtOk[k] = inb ? 16 : 8;   // 8 marks "slot active, zero-fill"
            int cgy = gy < 0 ? 0 : (gy >= HH ? HH - 1 : gy);
            int cgx = gx < 0 ? 0 : (gx > WW - 4 ? WW - 4 : gx);
            tgtG0[k] = tgtB + (size_t)c * (HH * WW) + (size_t)cgy * WW + cgx;
            tgtSm0[k] = (uint32_t)__cvta_generic_to_shared(&sTgt[0][c][r][4 * x4]);
        }
    }

    const uint32_t bufStrideS = (uint32_t)(sizeof(float) * CCHUNK * TY * SSTRIDE);
    const uint32_t bufStrideT = (uint32_t)(sizeof(float) * CCHUNK * TROWS * TSTRIDE);
    const size_t chunkG = (size_t)CCHUNK * HH * WW;   // global advance per chunk

    float acc[NDY][PPT];
    #pragma unroll
    for (int d = 0; d < NDY; ++d)
        #pragma unroll
        for (int p = 0; p < PPT; ++p) acc[d][p] = 0.0f;

    // ---- issue chunk 0 loads ----
    if (tid < NSRC4) cp16(srcSm0, srcG0, 16);
    #pragma unroll
    for (int k = 0; k < 3; ++k)
        if (tgtOk[k]) cp16(tgtSm0[k], tgtG0[k], tgtOk[k] == 16 ? 16 : 0);
    CP_COMMIT();

    const int tr = yy + dy + SR;
    const int tc = xg * PPT;

    for (int i = 0; i < NCHUNK; ++i) {
        // prefetch chunk i+1 into buffer (i+1)&1
        if (i + 1 < NCHUNK) {
            const uint32_t bs = ((i + 1) & 1) ? bufStrideS : 0u;
            const uint32_t bt = ((i + 1) & 1) ? bufStrideT : 0u;
            const size_t goff = (size_t)(i + 1) * chunkG;
            if (tid < NSRC4) cp16(srcSm0 + bs, srcG0 + goff, 16);
            #pragma unroll
            for (int k = 0; k < 3; ++k)
                if (tgtOk[k]) cp16(tgtSm0[k] + bt, tgtG0[k] + goff,
                                   tgtOk[k] == 16 ? 16 : 0);
        }
        CP_COMMIT();
        CP_WAIT1();          // chunk i complete (this thread's ops)
        __syncthreads();     // make all threads' chunk-i data visible

        const int bi = i & 1;
        #pragma unroll
        for (int c = 0; c < CCHUNK; ++c) {
            float4 s0 = *(const float4*)&sSrc[bi][c][yy][tc];
            float4 s1 = *(const float4*)&sSrc[bi][c][yy][tc + 4];
            float t[PPT + 2 * SR];
            #pragma unroll
            for (int q = 0; q < 4; ++q) {
                float4 tv = *(const float4*)&sTgt[bi][c][tr][tc + 4 * q];
                t[4 * q + 0] = tv.x; t[4 * q + 1] = tv.y;
                t[4 * q + 2] = tv.z; t[4 * q + 3] = tv.w;
            }
            float s[PPT] = {s0.x, s0.y, s0.z, s0.w, s1.x, s1.y, s1.z, s1.w};
            #pragma unroll
            for (int d = 0; d < NDY; ++d)
                #pragma unroll
                for (int p = 0; p < PPT; ++p)
                    acc[d][p] = fmaf(s[p], t[p + d], acc[d][p]);
        }
        __syncthreads();     // all reads of buffer bi done before it is refilled
    }

    // ---- epilogue: scale by 1/C, scatter to channel layout ----
    const float invC = 1.0f / (float)CH;
    const int gy  = ty0 + yy;
    const int gx0 = tx0 + tc;
    #pragma unroll
    for (int d = 0; d < NDY; ++d) {
        const int ch = chan_idx(dy, d - SR);
        float* o = out + (((size_t)b * ND + ch) * HH + gy) * WW + gx0;
        float4 v0 = make_float4(acc[d][0] * invC, acc[d][1] * invC,
                                acc[d][2] * invC, acc[d][3] * invC);
        float4 v1 = make_float4(acc[d][4] * invC, acc[d][5] * invC,
                                acc[d][6] * invC, acc[d][7] * invC);
        *(float4*)&o[0] = v0;
        *(float4*)&o[4] = v1;
    }
}

extern "C" void kernel_launch(void* const* d_in, const int* in_sizes, int n_in,
                              void* d_out, int out_size)
{
    const float* src = (const float*)d_in[0];
    const float* tgt = (const float*)d_in[1];
    float* out = (float*)d_out;

    dim3 grid(WW / TX, HH / TY, BB);   // (9, 20, 8)
    costvol_kernel<<<grid, NTHREADS>>>(src, tgt, out);
}